// round 13
// baseline (speedup 1.0000x reference)
#include <cuda_runtime.h>
#include <cuda_fp16.h>
#include <cstdint>
#include <math.h>

// ----------------------------------------------------------------------------
// GroupedSidechannelCrossAttention — fp16 mma.sync + stream-overlapped graph
//
//   All three projections as plain fp16 GEMMs (fp32 accum), K = 2048.
//   GEMM: CTA tile 128x256x64, 512 threads (16 warps, 2x8), warp tile 64x32,
//   4-stage cp.async pipeline, padded smem (72-half stride), K-major operands.
//
//   Graph:  conv ──┬─ Q gemm (fp16 out) ──────────┬─ attn ── O gemm
//                  └─ KV gemm ── reduce(fp16 out) ┘   (KV chain hidden under Q)
//
//   Attention operands (Q, KV) are fp16 (halves the L2-bound attn traffic);
//   all attention arithmetic stays fp32.
// ----------------------------------------------------------------------------

#define KK  2048
#define BM  128
#define BN  256
#define BK  64
#define ASTRIDE 72                        // 64 + 8 pad (halves)
#define A_BYTES (128 * ASTRIDE * 2)       // 18432
#define B_BYTES (256 * ASTRIDE * 2)       // 36864
#define STAGE_BYTES (A_BYTES + B_BYTES)   // 55296
#define NSTAGE 4
#define SMEM_DYN (NSTAGE * STAGE_BYTES + 256)   // 221440
#define KV_SPLITS 8
#define KV_NK 4                           // 2048 / (8*64)

// ------------------------- device scratch (static) --------------------------
__device__ __half g_xh  [2048u * 2048u];  // x fp16          [2048][2048]
__device__ __half g_csh [512u  * 2048u];  // ch.states fp16  [512][2048]
__device__ __half g_yh  [2048u * 2048u];  // y fp16          [2048][2048]
__device__ __half g_Wqh [2048u * 2048u];  // Wq^T fp16       [2048][2048]
__device__ __half g_Wkvh[1024u * 2048u];  // [Wk|Wv]^T fp16  [1024][2048]
__device__ __half g_Woh [2048u * 2048u];  // Wo^T fp16       [2048][2048]
__device__ __half g_Qh  [2048u * 2048u];  // fp16 Q
__device__ __half g_KVh [512u  * 1024u];  // fp16 [k | v]
__device__ float  g_KVp [KV_SPLITS * 512u * 1024u]; // split-K fp32 partials

// ----------------------------- helpers --------------------------------------
__device__ __forceinline__ uint32_t smem_u32(const void* p) {
    return (uint32_t)__cvta_generic_to_shared(p);
}
__device__ __forceinline__ void cp16(uint32_t dst, const void* src) {
    asm volatile("cp.async.cg.shared.global [%0], [%1], 16;\n" :: "r"(dst), "l"(src));
}
__device__ __forceinline__ void cp_commit() { asm volatile("cp.async.commit_group;\n" ::: "memory"); }
__device__ __forceinline__ void cp_wait0()  { asm volatile("cp.async.wait_group 0;\n" ::: "memory"); }
__device__ __forceinline__ void cp_wait1()  { asm volatile("cp.async.wait_group 1;\n" ::: "memory"); }
__device__ __forceinline__ void cp_wait2()  { asm volatile("cp.async.wait_group 2;\n" ::: "memory"); }

// --------------------------- consolidated converts ---------------------------
// Block ranges:
//   [0, 4096)      : x cast (4 elems/thread)
//   [4096, 5120)   : cs cast
//   [5120, 9216)   : Wq transpose (32x32 tiles)
//   [9216, 10240)  : Wk transpose -> rows [0,512)   of g_Wkvh
//   [10240, 11264) : Wv transpose -> rows [512,1024)
//   [11264, 15360) : Wo transpose
__global__ __launch_bounds__(256)
void conv_all_kernel(const float* __restrict__ x,  const float* __restrict__ cs,
                     const float* __restrict__ Wq, const float* __restrict__ Wk,
                     const float* __restrict__ Wv, const float* __restrict__ Wo) {
    __shared__ float tile[32][33];
    const int bid = blockIdx.x;
    const int t = threadIdx.x;

    if (bid < 5120) {                      // ---- plain casts ----
        const float* src; __half* dst; unsigned base;
        if (bid < 4096) { src = x;  dst = g_xh;  base = (unsigned)bid * 1024u; }
        else            { src = cs; dst = g_csh; base = (unsigned)(bid - 4096) * 1024u; }
        unsigned i = base + t * 4u;
        float4 v = *(const float4*)(src + i);
        *(__half2*)(dst + i)     = __floats2half2_rn(v.x, v.y);
        *(__half2*)(dst + i + 2) = __floats2half2_rn(v.z, v.w);
        return;
    }

    // ---- weight transposes ----
    const float* W; __half* dst; int N, rowofs, local;
    if (bid < 9216)       { W = Wq; dst = g_Wqh;  N = 2048; rowofs = 0;   local = bid - 5120;  }
    else if (bid < 10240) { W = Wk; dst = g_Wkvh; N = 512;  rowofs = 0;   local = bid - 9216;  }
    else if (bid < 11264) { W = Wv; dst = g_Wkvh; N = 512;  rowofs = 512; local = bid - 10240; }
    else                  { W = Wo; dst = g_Woh;  N = 2048; rowofs = 0;   local = bid - 11264; }
    const int wtiles = N >> 5;
    const int n0 = (local % wtiles) * 32;
    const int k0 = (local / wtiles) * 32;

    const int ln = t & 31, lk = t >> 5;
    #pragma unroll
    for (int j = 0; j < 4; j++)
        tile[lk + j * 8][ln] = W[(size_t)(k0 + lk + j * 8) * N + n0 + ln];
    __syncthreads();
    const int on = t >> 3;
    const int ok = (t & 7) * 4;
    __half2 p0 = __floats2half2_rn(tile[ok][on],     tile[ok + 1][on]);
    __half2 p1 = __floats2half2_rn(tile[ok + 2][on], tile[ok + 3][on]);
    size_t base = (size_t)(rowofs + n0 + on) * 2048u + k0 + ok;
    *(__half2*)(dst + base)     = p0;
    *(__half2*)(dst + base + 2) = p1;
}

// ----------------------------- GEMM kernel -----------------------------------
// C = A[M][2048] * (W[N][2048])^T, fp16 in / fp32 accum.
// which: 0=Q (fp16 out), 1=KV partial (fp32, K slice per blockIdx.z), 2=O (fp32 + gate)
__global__ __launch_bounds__(512)
void gemm_mma_kernel(int which, float* __restrict__ outp,
                     const float* __restrict__ gate, int N, int nk) {
    const __half *A, *B;
    if      (which == 0) { A = g_xh;  B = g_Wqh;  }
    else if (which == 1) { A = g_csh; B = g_Wkvh; }
    else                 { A = g_yh;  B = g_Woh;  }

    extern __shared__ char dynsmem[];
    const uint32_t sbase = (smem_u32(dynsmem) + 255u) & ~255u;

    const int t = threadIdx.x;
    const int lane = t & 31;
    const int wid  = t >> 5;
    const int m_base = blockIdx.y * BM;
    const int n_base = blockIdx.x * BN;
    const int kbeg   = blockIdx.z * (nk * BK);

    // warp grid: 2 along M (64 rows) x 8 along N (32 cols)
    const int wm = (wid >> 3) * 64;
    const int wn = (wid & 7) * 32;

    auto issue = [&](int s, int kglob) {
        uint32_t aT = sbase + s * STAGE_BYTES;
        uint32_t bT = aT + A_BYTES;
        #pragma unroll
        for (int j = 0; j < 2; j++) {            // A: 128 rows x 8 chunks of 16B
            int e = t + j * 512;
            int row = e >> 3, c = e & 7;
            cp16(aT + row * (ASTRIDE * 2) + c * 16,
                 A + (size_t)(m_base + row) * KK + kglob + c * 8);
        }
        #pragma unroll
        for (int j = 0; j < 4; j++) {            // B: 256 rows x 8 chunks of 16B
            int e = t + j * 512;
            int row = e >> 3, c = e & 7;
            cp16(bT + row * (ASTRIDE * 2) + c * 16,
                 B + (size_t)(n_base + row) * 2048u + kglob + c * 8);
        }
        cp_commit();
    };

    float acc[4][4][4];
    #pragma unroll
    for (int i = 0; i < 4; i++)
        #pragma unroll
        for (int j = 0; j < 4; j++)
            #pragma unroll
            for (int r = 0; r < 4; r++) acc[i][j][r] = 0.f;

    issue(0, kbeg);
    if (nk > 1) issue(1, kbeg + BK);
    if (nk > 2) issue(2, kbeg + 2 * BK);

    const uint32_t a_off = (uint32_t)((wm + (lane & 15)) * (ASTRIDE * 2) + ((lane >> 4) * 8) * 2);
    const uint32_t b_off = (uint32_t)((wn + ((lane >> 4) & 1) * 8 + (lane & 7)) * (ASTRIDE * 2)
                                      + (((lane >> 3) & 1) * 8) * 2);

    for (int i = 0; i < nk; i++) {
        if (i + 3 <= nk)      cp_wait2();
        else if (i + 2 <= nk) cp_wait1();
        else                  cp_wait0();
        __syncthreads();
        if (i + 3 < nk) issue((i + 3) & 3, kbeg + (i + 3) * BK);

        const uint32_t aT = sbase + (i & 3) * STAGE_BYTES;
        const uint32_t bT = aT + A_BYTES;

        #pragma unroll
        for (int ks = 0; ks < 4; ks++) {
            const uint32_t kb = ks * 32;
            uint32_t a[4][4], bb[2][4];
            #pragma unroll
            for (int mi = 0; mi < 4; mi++) {
                uint32_t addr = aT + a_off + mi * (16 * ASTRIDE * 2) + kb;
                asm volatile("ldmatrix.sync.aligned.m8n8.x4.shared.b16 {%0,%1,%2,%3}, [%4];\n"
                    : "=r"(a[mi][0]), "=r"(a[mi][1]), "=r"(a[mi][2]), "=r"(a[mi][3])
                    : "r"(addr));
            }
            #pragma unroll
            for (int nn = 0; nn < 2; nn++) {
                uint32_t addr = bT + b_off + nn * (16 * ASTRIDE * 2) + kb;
                asm volatile("ldmatrix.sync.aligned.m8n8.x4.shared.b16 {%0,%1,%2,%3}, [%4];\n"
                    : "=r"(bb[nn][0]), "=r"(bb[nn][1]), "=r"(bb[nn][2]), "=r"(bb[nn][3])
                    : "r"(addr));
            }
            #pragma unroll
            for (int mi = 0; mi < 4; mi++)
                #pragma unroll
                for (int ni = 0; ni < 4; ni++) {
                    asm volatile(
                        "mma.sync.aligned.m16n8k16.row.col.f32.f16.f16.f32 "
                        "{%0,%1,%2,%3}, {%4,%5,%6,%7}, {%8,%9}, {%0,%1,%2,%3};\n"
                        : "+f"(acc[mi][ni][0]), "+f"(acc[mi][ni][1]),
                          "+f"(acc[mi][ni][2]), "+f"(acc[mi][ni][3])
                        : "r"(a[mi][0]), "r"(a[mi][1]), "r"(a[mi][2]), "r"(a[mi][3]),
                          "r"(bb[ni >> 1][(ni & 1) * 2]), "r"(bb[ni >> 1][(ni & 1) * 2 + 1]));
                }
        }
    }

    const int g8 = lane >> 2;
    const int t4 = lane & 3;
    if (which == 0) {
        // Q epilogue: fp16 stores into g_Qh
        #pragma unroll
        for (int mi = 0; mi < 4; mi++)
            #pragma unroll
            for (int ni = 0; ni < 4; ni++) {
                size_t row0 = (size_t)m_base + wm + mi * 16 + g8;
                size_t col  = (size_t)n_base + wn + ni * 8 + t4 * 2;
                *(__half2*)(g_Qh + row0 * N + col) =
                    __floats2half2_rn(acc[mi][ni][0], acc[mi][ni][1]);
                *(__half2*)(g_Qh + (row0 + 8) * N + col) =
                    __floats2half2_rn(acc[mi][ni][2], acc[mi][ni][3]);
            }
    } else {
        float* C = (which == 1) ? (g_KVp + (size_t)blockIdx.z * (512u * 1024u)) : outp;
        const float gs = (which == 2) ? tanhf(gate[0]) : 1.0f;
        #pragma unroll
        for (int mi = 0; mi < 4; mi++)
            #pragma unroll
            for (int ni = 0; ni < 4; ni++) {
                size_t row0 = (size_t)m_base + wm + mi * 16 + g8;
                size_t col  = (size_t)n_base + wn + ni * 8 + t4 * 2;
                C[row0 * N + col]           = acc[mi][ni][0] * gs;
                C[row0 * N + col + 1]       = acc[mi][ni][1] * gs;
                C[(row0 + 8) * N + col]     = acc[mi][ni][2] * gs;
                C[(row0 + 8) * N + col + 1] = acc[mi][ni][3] * gs;
            }
    }
}

// ------------------------- split-K reduce (KV, fp16 out) ----------------------
__global__ void reduce_kv_kernel() {
    unsigned i4 = (blockIdx.x * 256u + threadIdx.x) * 4u;   // 512 blocks
    float4 s = make_float4(0.f, 0.f, 0.f, 0.f);
    #pragma unroll
    for (int p = 0; p < KV_SPLITS; p++) {
        float4 v = *(const float4*)(g_KVp + (size_t)p * (512u * 1024u) + i4);
        s.x += v.x; s.y += v.y; s.z += v.z; s.w += v.w;
    }
    *(__half2*)(g_KVh + i4)     = __floats2half2_rn(s.x, s.y);
    *(__half2*)(g_KVh + i4 + 2) = __floats2half2_rn(s.z, s.w);
}

// --------------------------- attention kernel --------------------------------
// 1 block per token. g_KVh row: [(b*8+ch)*32 + latent][ k: g*128+d | v: 512+g*128+d ]
// All operands fp16, all arithmetic fp32. Writes y fp16 into g_yh.
__global__ __launch_bounds__(256)
void attn_kernel(const int* __restrict__ mask) {
    const int tg = blockIdx.x;
    const int b  = tg >> 10;
    const int ch = mask[tg];
    const size_t kvrow0 = (size_t)((b * 8 + ch) * 32);

    __shared__ __half q_s[2048];
    __shared__ float attn_s[8][32];

    ((uint4*)q_s)[threadIdx.x] = ((const uint4*)(g_Qh + (size_t)tg * 2048))[threadIdx.x];
    __syncthreads();

    const int wid = threadIdx.x >> 5;
    const int lane = threadIdx.x & 31;
    const float scale = 0.08838834764831845f;   // 1/sqrt(128)

    for (int hh = 0; hh < 2; hh++) {
        const int h = wid * 2 + hh;
        const int g = h >> 2;

        // ---- scores: lane = latent, fp32 dot over d=128 (fp16 operands) ----
        const __half* krow = g_KVh + (kvrow0 + lane) * 1024 + g * 128;
        const __half* qh = q_s + h * 128;
        float s = 0.f;
        #pragma unroll
        for (int c = 0; c < 16; c++) {                 // 16 x 16B
            uint4 k4 = *(const uint4*)(krow + c * 8);
            uint4 q4 = *(const uint4*)(qh + c * 8);
            float2 ka = __half22float2(*(__half2*)&k4.x), qa = __half22float2(*(__half2*)&q4.x);
            float2 kb = __half22float2(*(__half2*)&k4.y), qb = __half22float2(*(__half2*)&q4.y);
            float2 kc = __half22float2(*(__half2*)&k4.z), qc = __half22float2(*(__half2*)&q4.z);
            float2 kd = __half22float2(*(__half2*)&k4.w), qd = __half22float2(*(__half2*)&q4.w);
            s += ka.x * qa.x + ka.y * qa.y + kb.x * qb.x + kb.y * qb.y
               + kc.x * qc.x + kc.y * qc.y + kd.x * qd.x + kd.y * qd.y;
        }
        s *= scale;

        // ---- softmax over 32 latents ----
        float m = s;
        #pragma unroll
        for (int o = 16; o; o >>= 1) m = fmaxf(m, __shfl_xor_sync(0xffffffffu, m, o));
        float e = __expf(s - m);
        float sum = e;
        #pragma unroll
        for (int o = 16; o; o >>= 1) sum += __shfl_xor_sync(0xffffffffu, sum, o);
        attn_s[wid][lane] = e / sum;
        __syncwarp();

        // ---- AV: lane covers d = lane*4..+3, sum over 32 latents ----
        float4 acc = make_float4(0.f, 0.f, 0.f, 0.f);
        const __half* vbase = g_KVh + kvrow0 * 1024 + 512 + g * 128 + lane * 4;
        #pragma unroll
        for (int kl = 0; kl < 32; kl++) {
            float w = attn_s[wid][kl];
            uint2 v2 = *(const uint2*)(vbase + (size_t)kl * 1024);
            float2 f0 = __half22float2(*(__half2*)&v2.x);
            float2 f1 = __half22float2(*(__half2*)&v2.y);
            acc.x += w * f0.x; acc.y += w * f0.y; acc.z += w * f1.x; acc.w += w * f1.y;
        }

        size_t base = (size_t)tg * 2048u + h * 128 + lane * 4;
        *(__half2*)(g_yh + base)     = __floats2half2_rn(acc.x, acc.y);
        *(__half2*)(g_yh + base + 2) = __floats2half2_rn(acc.z, acc.w);
        __syncwarp();
    }
}

// ------------------------------- launcher ------------------------------------
extern "C" void kernel_launch(void* const* d_in, const int* in_sizes, int n_in,
                              void* d_out, int out_size) {
    const float* x    = (const float*)d_in[0];   // (2,1024,2048)
    const float* cs   = (const float*)d_in[1];   // (2,8,32,2048)
    const int*   mask = (const int*)  d_in[2];   // (2,1024)
    const float* Wq   = (const float*)d_in[3];   // (2048,2048)
    const float* Wk   = (const float*)d_in[4];   // (2048,512)
    const float* Wv   = (const float*)d_in[5];   // (2048,512)
    const float* Wo   = (const float*)d_in[6];   // (2048,2048)
    const float* gate = (const float*)d_in[7];   // (1,)
    float* out = (float*)d_out;

    static cudaStream_t s1 = nullptr;
    static cudaEvent_t ev_fork = nullptr, ev_join = nullptr;
    if (!s1) {
        cudaStreamCreateWithFlags(&s1, cudaStreamNonBlocking);
        cudaEventCreateWithFlags(&ev_fork, cudaEventDisableTiming);
        cudaEventCreateWithFlags(&ev_join, cudaEventDisableTiming);
        cudaFuncSetAttribute(gemm_mma_kernel,
                             cudaFuncAttributeMaxDynamicSharedMemorySize, SMEM_DYN);
    }

    // 1) all converts (one launch, main stream)
    conv_all_kernel<<<15360, 256>>>(x, cs, Wq, Wk, Wv, Wo);
    cudaEventRecord(ev_fork, 0);

    // 2a) side stream: KV partials + reduce (hidden under Q GEMM)
    cudaStreamWaitEvent(s1, ev_fork, 0);
    gemm_mma_kernel<<<dim3(1024 / BN, 512 / BM, KV_SPLITS), 512, SMEM_DYN, s1>>>(1, nullptr, gate, 1024, KV_NK);
    reduce_kv_kernel<<<512, 256, 0, s1>>>();
    cudaEventRecord(ev_join, s1);

    // 2b) main stream: Q = x @ Wq (fp16 out)
    gemm_mma_kernel<<<dim3(2048 / BN, 2048 / BM, 1), 512, SMEM_DYN>>>(0, nullptr, gate, 2048, KK / BK);

    // 3) join, then attention -> y (fp16)
    cudaStreamWaitEvent(0, ev_join, 0);
    attn_kernel<<<2048, 256>>>(mask);

    // 4) out = (y @ Wo) * tanh(gate)
    gemm_mma_kernel<<<dim3(2048 / BN, 2048 / BM, 1), 512, SMEM_DYN>>>(2, out, gate, 2048, KK / BK);
}

// round 14
// speedup vs baseline: 1.5100x; 1.5100x over previous
#include <cuda_runtime.h>
#include <cuda_fp16.h>
#include <cstdint>
#include <math.h>

// ----------------------------------------------------------------------------
// GroupedSidechannelCrossAttention — fp16 mma.sync, 2-CTA/SM occupancy edition
//
//   Profile evidence (R13): tensor=47%, occ=24.7%, DRAM=2.2% -> GEMM is
//   latency-bound at 1 CTA/SM. Fix: CTA tile 128x128x64, 256 threads,
//   3-stage cp.async (110.8KB smem), __launch_bounds__(256,2) -> 2 CTAs/SM,
//   grid 256 = 2 full waves of independent CTAs per SM.
//
//   Numerics: pure fp16 GEMMs (fp32 accum), fp16 Q/KV/y attention operands,
//   fp32 attention arithmetic. Measured rel_err 6.07e-4 < 1e-3.
//
//   Sequential graph (no streams — R13 showed same-resource overlap regresses):
//   conv -> Q gemm -> KV gemm(splitK=8) -> reduce -> attn -> O gemm.
// ----------------------------------------------------------------------------

#define KK  2048
#define BM  128
#define BN  128
#define BK  64
#define ASTRIDE 72                        // 64 + 8 pad (halves)
#define A_BYTES (128 * ASTRIDE * 2)       // 18432
#define B_BYTES (128 * ASTRIDE * 2)       // 18432
#define STAGE_BYTES (A_BYTES + B_BYTES)   // 36864
#define NSTAGE 3
#define SMEM_DYN (NSTAGE * STAGE_BYTES + 256)   // 110848 -> 2 CTAs/SM
#define KV_SPLITS 8
#define KV_NK 4                           // 2048 / (8*64)

// ------------------------- device scratch (static) --------------------------
__device__ __half g_xh  [2048u * 2048u];  // x fp16          [2048][2048]
__device__ __half g_csh [512u  * 2048u];  // ch.states fp16  [512][2048]
__device__ __half g_yh  [2048u * 2048u];  // y fp16          [2048][2048]
__device__ __half g_Wqh [2048u * 2048u];  // Wq^T fp16       [2048][2048]
__device__ __half g_Wkvh[1024u * 2048u];  // [Wk|Wv]^T fp16  [1024][2048]
__device__ __half g_Woh [2048u * 2048u];  // Wo^T fp16       [2048][2048]
__device__ __half g_Qh  [2048u * 2048u];  // fp16 Q
__device__ __half g_KVh [512u  * 1024u];  // fp16 [k | v]
__device__ float  g_KVp [KV_SPLITS * 512u * 1024u]; // split-K fp32 partials

// ----------------------------- helpers --------------------------------------
__device__ __forceinline__ uint32_t smem_u32(const void* p) {
    return (uint32_t)__cvta_generic_to_shared(p);
}
__device__ __forceinline__ void cp16(uint32_t dst, const void* src) {
    asm volatile("cp.async.cg.shared.global [%0], [%1], 16;\n" :: "r"(dst), "l"(src));
}
__device__ __forceinline__ void cp_commit() { asm volatile("cp.async.commit_group;\n" ::: "memory"); }
__device__ __forceinline__ void cp_wait0()  { asm volatile("cp.async.wait_group 0;\n" ::: "memory"); }
__device__ __forceinline__ void cp_wait1()  { asm volatile("cp.async.wait_group 1;\n" ::: "memory"); }

// --------------------------- consolidated converts ---------------------------
// Block ranges:
//   [0, 4096)      : x cast (4 elems/thread)
//   [4096, 5120)   : cs cast
//   [5120, 9216)   : Wq transpose (32x32 tiles)
//   [9216, 10240)  : Wk transpose -> rows [0,512)   of g_Wkvh
//   [10240, 11264) : Wv transpose -> rows [512,1024)
//   [11264, 15360) : Wo transpose
__global__ __launch_bounds__(256)
void conv_all_kernel(const float* __restrict__ x,  const float* __restrict__ cs,
                     const float* __restrict__ Wq, const float* __restrict__ Wk,
                     const float* __restrict__ Wv, const float* __restrict__ Wo) {
    __shared__ float tile[32][33];
    const int bid = blockIdx.x;
    const int t = threadIdx.x;

    if (bid < 5120) {                      // ---- plain casts ----
        const float* src; __half* dst; unsigned base;
        if (bid < 4096) { src = x;  dst = g_xh;  base = (unsigned)bid * 1024u; }
        else            { src = cs; dst = g_csh; base = (unsigned)(bid - 4096) * 1024u; }
        unsigned i = base + t * 4u;
        float4 v = *(const float4*)(src + i);
        *(__half2*)(dst + i)     = __floats2half2_rn(v.x, v.y);
        *(__half2*)(dst + i + 2) = __floats2half2_rn(v.z, v.w);
        return;
    }

    // ---- weight transposes ----
    const float* W; __half* dst; int N, rowofs, local;
    if (bid < 9216)       { W = Wq; dst = g_Wqh;  N = 2048; rowofs = 0;   local = bid - 5120;  }
    else if (bid < 10240) { W = Wk; dst = g_Wkvh; N = 512;  rowofs = 0;   local = bid - 9216;  }
    else if (bid < 11264) { W = Wv; dst = g_Wkvh; N = 512;  rowofs = 512; local = bid - 10240; }
    else                  { W = Wo; dst = g_Woh;  N = 2048; rowofs = 0;   local = bid - 11264; }
    const int wtiles = N >> 5;
    const int n0 = (local % wtiles) * 32;
    const int k0 = (local / wtiles) * 32;

    const int ln = t & 31, lk = t >> 5;
    #pragma unroll
    for (int j = 0; j < 4; j++)
        tile[lk + j * 8][ln] = W[(size_t)(k0 + lk + j * 8) * N + n0 + ln];
    __syncthreads();
    const int on = t >> 3;
    const int ok = (t & 7) * 4;
    __half2 p0 = __floats2half2_rn(tile[ok][on],     tile[ok + 1][on]);
    __half2 p1 = __floats2half2_rn(tile[ok + 2][on], tile[ok + 3][on]);
    size_t base = (size_t)(rowofs + n0 + on) * 2048u + k0 + ok;
    *(__half2*)(dst + base)     = p0;
    *(__half2*)(dst + base + 2) = p1;
}

// ----------------------------- GEMM kernel -----------------------------------
// C = A[M][2048] * (W[N][2048])^T, fp16 in / fp32 accum.
// CTA tile 128x128x64, 256 threads (8 warps, 2x4), warp tile 64x32, 2 CTAs/SM.
// which: 0=Q (fp16 out), 1=KV partial (fp32, K slice per blockIdx.z), 2=O (fp32+gate)
__global__ __launch_bounds__(256, 2)
void gemm_mma_kernel(int which, float* __restrict__ outp,
                     const float* __restrict__ gate, int N, int nk) {
    const __half *A, *B;
    if      (which == 0) { A = g_xh;  B = g_Wqh;  }
    else if (which == 1) { A = g_csh; B = g_Wkvh; }
    else                 { A = g_yh;  B = g_Woh;  }

    extern __shared__ char dynsmem[];
    const uint32_t sbase = (smem_u32(dynsmem) + 255u) & ~255u;

    const int t = threadIdx.x;
    const int lane = t & 31;
    const int wid  = t >> 5;
    const int m_base = blockIdx.y * BM;
    const int n_base = blockIdx.x * BN;
    const int kbeg   = blockIdx.z * (nk * BK);

    // warp grid: 2 along M (64 rows) x 4 along N (32 cols)
    const int wm = (wid >> 2) * 64;
    const int wn = (wid & 3) * 32;

    auto issue = [&](int s, int kglob) {
        uint32_t aT = sbase + s * STAGE_BYTES;
        uint32_t bT = aT + A_BYTES;
        #pragma unroll
        for (int j = 0; j < 4; j++) {            // A: 128 rows x 8 chunks of 16B
            int e = t + j * 256;
            int row = e >> 3, c = e & 7;
            cp16(aT + row * (ASTRIDE * 2) + c * 16,
                 A + (size_t)(m_base + row) * KK + kglob + c * 8);
        }
        #pragma unroll
        for (int j = 0; j < 4; j++) {            // B: 128 rows x 8 chunks of 16B
            int e = t + j * 256;
            int row = e >> 3, c = e & 7;
            cp16(bT + row * (ASTRIDE * 2) + c * 16,
                 B + (size_t)(n_base + row) * 2048u + kglob + c * 8);
        }
        cp_commit();
    };

    float acc[4][4][4];
    #pragma unroll
    for (int i = 0; i < 4; i++)
        #pragma unroll
        for (int j = 0; j < 4; j++)
            #pragma unroll
            for (int r = 0; r < 4; r++) acc[i][j][r] = 0.f;

    issue(0, kbeg);
    if (nk > 1) issue(1, kbeg + BK);

    const uint32_t a_off = (uint32_t)((wm + (lane & 15)) * (ASTRIDE * 2) + ((lane >> 4) * 8) * 2);
    const uint32_t b_off = (uint32_t)((wn + ((lane >> 4) & 1) * 8 + (lane & 7)) * (ASTRIDE * 2)
                                      + (((lane >> 3) & 1) * 8) * 2);

    for (int i = 0; i < nk; i++) {
        if (i < nk - 1) cp_wait1(); else cp_wait0();
        __syncthreads();
        if (i + 2 < nk) issue((i + 2) % 3, kbeg + (i + 2) * BK);

        const uint32_t aT = sbase + (i % 3) * STAGE_BYTES;
        const uint32_t bT = aT + A_BYTES;

        #pragma unroll
        for (int ks = 0; ks < 4; ks++) {
            const uint32_t kb = ks * 32;   // 16 halves = 32 bytes
            uint32_t a[4][4], bb[2][4];
            #pragma unroll
            for (int mi = 0; mi < 4; mi++) {
                uint32_t addr = aT + a_off + mi * (16 * ASTRIDE * 2) + kb;
                asm volatile("ldmatrix.sync.aligned.m8n8.x4.shared.b16 {%0,%1,%2,%3}, [%4];\n"
                    : "=r"(a[mi][0]), "=r"(a[mi][1]), "=r"(a[mi][2]), "=r"(a[mi][3])
                    : "r"(addr));
            }
            #pragma unroll
            for (int nn = 0; nn < 2; nn++) {
                uint32_t addr = bT + b_off + nn * (16 * ASTRIDE * 2) + kb;
                asm volatile("ldmatrix.sync.aligned.m8n8.x4.shared.b16 {%0,%1,%2,%3}, [%4];\n"
                    : "=r"(bb[nn][0]), "=r"(bb[nn][1]), "=r"(bb[nn][2]), "=r"(bb[nn][3])
                    : "r"(addr));
            }
            #pragma unroll
            for (int mi = 0; mi < 4; mi++)
                #pragma unroll
                for (int ni = 0; ni < 4; ni++) {
                    asm volatile(
                        "mma.sync.aligned.m16n8k16.row.col.f32.f16.f16.f32 "
                        "{%0,%1,%2,%3}, {%4,%5,%6,%7}, {%8,%9}, {%0,%1,%2,%3};\n"
                        : "+f"(acc[mi][ni][0]), "+f"(acc[mi][ni][1]),
                          "+f"(acc[mi][ni][2]), "+f"(acc[mi][ni][3])
                        : "r"(a[mi][0]), "r"(a[mi][1]), "r"(a[mi][2]), "r"(a[mi][3]),
                          "r"(bb[ni >> 1][(ni & 1) * 2]), "r"(bb[ni >> 1][(ni & 1) * 2 + 1]));
                }
        }
    }

    const int g8 = lane >> 2;
    const int t4 = lane & 3;
    if (which == 0) {
        // Q epilogue: fp16 stores into g_Qh
        #pragma unroll
        for (int mi = 0; mi < 4; mi++)
            #pragma unroll
            for (int ni = 0; ni < 4; ni++) {
                size_t row0 = (size_t)m_base + wm + mi * 16 + g8;
                size_t col  = (size_t)n_base + wn + ni * 8 + t4 * 2;
                *(__half2*)(g_Qh + row0 * N + col) =
                    __floats2half2_rn(acc[mi][ni][0], acc[mi][ni][1]);
                *(__half2*)(g_Qh + (row0 + 8) * N + col) =
                    __floats2half2_rn(acc[mi][ni][2], acc[mi][ni][3]);
            }
    } else {
        float* C = (which == 1) ? (g_KVp + (size_t)blockIdx.z * (512u * 1024u)) : outp;
        const float gs = (which == 2) ? tanhf(gate[0]) : 1.0f;
        #pragma unroll
        for (int mi = 0; mi < 4; mi++)
            #pragma unroll
            for (int ni = 0; ni < 4; ni++) {
                size_t row0 = (size_t)m_base + wm + mi * 16 + g8;
                size_t col  = (size_t)n_base + wn + ni * 8 + t4 * 2;
                C[row0 * N + col]           = acc[mi][ni][0] * gs;
                C[row0 * N + col + 1]       = acc[mi][ni][1] * gs;
                C[(row0 + 8) * N + col]     = acc[mi][ni][2] * gs;
                C[(row0 + 8) * N + col + 1] = acc[mi][ni][3] * gs;
            }
    }
}

// ------------------------- split-K reduce (KV, fp16 out) ----------------------
__global__ void reduce_kv_kernel() {
    unsigned i4 = (blockIdx.x * 256u + threadIdx.x) * 4u;   // 512 blocks
    float4 s = make_float4(0.f, 0.f, 0.f, 0.f);
    #pragma unroll
    for (int p = 0; p < KV_SPLITS; p++) {
        float4 v = *(const float4*)(g_KVp + (size_t)p * (512u * 1024u) + i4);
        s.x += v.x; s.y += v.y; s.z += v.z; s.w += v.w;
    }
    *(__half2*)(g_KVh + i4)     = __floats2half2_rn(s.x, s.y);
    *(__half2*)(g_KVh + i4 + 2) = __floats2half2_rn(s.z, s.w);
}

// --------------------------- attention kernel --------------------------------
// 1 block per token. g_KVh row: [(b*8+ch)*32 + latent][ k: g*128+d | v: 512+g*128+d ]
// All operands fp16, all arithmetic fp32. Writes y fp16 into g_yh.
__global__ __launch_bounds__(256)
void attn_kernel(const int* __restrict__ mask) {
    const int tg = blockIdx.x;
    const int b  = tg >> 10;
    const int ch = mask[tg];
    const size_t kvrow0 = (size_t)((b * 8 + ch) * 32);

    __shared__ __half q_s[2048];
    __shared__ float attn_s[8][32];

    ((uint4*)q_s)[threadIdx.x] = ((const uint4*)(g_Qh + (size_t)tg * 2048))[threadIdx.x];
    __syncthreads();

    const int wid = threadIdx.x >> 5;
    const int lane = threadIdx.x & 31;
    const float scale = 0.08838834764831845f;   // 1/sqrt(128)

    for (int hh = 0; hh < 2; hh++) {
        const int h = wid * 2 + hh;
        const int g = h >> 2;

        // ---- scores: lane = latent, fp32 dot over d=128 (fp16 operands) ----
        const __half* krow = g_KVh + (kvrow0 + lane) * 1024 + g * 128;
        const __half* qh = q_s + h * 128;
        float s = 0.f;
        #pragma unroll
        for (int c = 0; c < 16; c++) {                 // 16 x 16B
            uint4 k4 = *(const uint4*)(krow + c * 8);
            uint4 q4 = *(const uint4*)(qh + c * 8);
            float2 ka = __half22float2(*(__half2*)&k4.x), qa = __half22float2(*(__half2*)&q4.x);
            float2 kb = __half22float2(*(__half2*)&k4.y), qb = __half22float2(*(__half2*)&q4.y);
            float2 kc = __half22float2(*(__half2*)&k4.z), qc = __half22float2(*(__half2*)&q4.z);
            float2 kd = __half22float2(*(__half2*)&k4.w), qd = __half22float2(*(__half2*)&q4.w);
            s += ka.x * qa.x + ka.y * qa.y + kb.x * qb.x + kb.y * qb.y
               + kc.x * qc.x + kc.y * qc.y + kd.x * qd.x + kd.y * qd.y;
        }
        s *= scale;

        // ---- softmax over 32 latents ----
        float m = s;
        #pragma unroll
        for (int o = 16; o; o >>= 1) m = fmaxf(m, __shfl_xor_sync(0xffffffffu, m, o));
        float e = __expf(s - m);
        float sum = e;
        #pragma unroll
        for (int o = 16; o; o >>= 1) sum += __shfl_xor_sync(0xffffffffu, sum, o);
        attn_s[wid][lane] = e / sum;
        __syncwarp();

        // ---- AV: lane covers d = lane*4..+3, sum over 32 latents ----
        float4 acc = make_float4(0.f, 0.f, 0.f, 0.f);
        const __half* vbase = g_KVh + kvrow0 * 1024 + 512 + g * 128 + lane * 4;
        #pragma unroll
        for (int kl = 0; kl < 32; kl++) {
            float w = attn_s[wid][kl];
            uint2 v2 = *(const uint2*)(vbase + (size_t)kl * 1024);
            float2 f0 = __half22float2(*(__half2*)&v2.x);
            float2 f1 = __half22float2(*(__half2*)&v2.y);
            acc.x += w * f0.x; acc.y += w * f0.y; acc.z += w * f1.x; acc.w += w * f1.y;
        }

        size_t base = (size_t)tg * 2048u + h * 128 + lane * 4;
        *(__half2*)(g_yh + base)     = __floats2half2_rn(acc.x, acc.y);
        *(__half2*)(g_yh + base + 2) = __floats2half2_rn(acc.z, acc.w);
        __syncwarp();
    }
}

// ------------------------------- launcher ------------------------------------
extern "C" void kernel_launch(void* const* d_in, const int* in_sizes, int n_in,
                              void* d_out, int out_size) {
    const float* x    = (const float*)d_in[0];   // (2,1024,2048)
    const float* cs   = (const float*)d_in[1];   // (2,8,32,2048)
    const int*   mask = (const int*)  d_in[2];   // (2,1024)
    const float* Wq   = (const float*)d_in[3];   // (2048,2048)
    const float* Wk   = (const float*)d_in[4];   // (2048,512)
    const float* Wv   = (const float*)d_in[5];   // (2048,512)
    const float* Wo   = (const float*)d_in[6];   // (2048,2048)
    const float* gate = (const float*)d_in[7];   // (1,)
    float* out = (float*)d_out;

    cudaFuncSetAttribute(gemm_mma_kernel,
                         cudaFuncAttributeMaxDynamicSharedMemorySize, SMEM_DYN);

    // 1) all converts (one launch)
    conv_all_kernel<<<15360, 256>>>(x, cs, Wq, Wk, Wv, Wo);

    // 2) Q = x @ Wq (fp16 out): 16x16 = 256 CTAs, 2/SM
    gemm_mma_kernel<<<dim3(2048 / BN, 2048 / BM, 1), 256, SMEM_DYN>>>(0, nullptr, gate, 2048, KK / BK);

    // 3) [K|V] partials (512 x 1024), split-K=8 -> 8x4x8 = 256 CTAs
    gemm_mma_kernel<<<dim3(1024 / BN, 512 / BM, KV_SPLITS), 256, SMEM_DYN>>>(1, nullptr, gate, 1024, KV_NK);
    reduce_kv_kernel<<<512, 256>>>();

    // 4) attention -> y (fp16)
    attn_kernel<<<2048, 256>>>(mask);

    // 5) out = (y @ Wo) * tanh(gate)   [profiled launch #6]
    gemm_mma_kernel<<<dim3(2048 / BN, 2048 / BM, 1), 256, SMEM_DYN>>>(2, out, gate, 2048, KK / BK);
}